// round 9
// baseline (speedup 1.0000x reference)
#include <cuda_runtime.h>
#include <mma.h>
#include <cstdint>

using namespace nvcuda;

#define D_MODEL 1024
#define N_HEADS 16
#define DK      64
#define BATCH   2
#define SEQ     2048
#define MTOT    (BATCH*SEQ)
#define QKVLD   (3*D_MODEL)   // 3072

// ------------------------- scratch (no allocs allowed) ----------------------
__device__ float g_xt [(size_t)MTOT * D_MODEL];           // tf32-rounded x
__device__ float g_wt [(size_t)4 * D_MODEL * D_MODEL];    // tf32-rounded Wq,Wk,Wv,Wo
__device__ float g_QKV[(size_t)MTOT * QKVLD];             // fused Q|K|V, ld=3072
__device__ float g_O  [(size_t)MTOT * D_MODEL];

// ------------------------- helpers ------------------------------------------
__device__ __forceinline__ float tf32r(float x) {
    uint32_t u;
    asm("cvt.rna.tf32.f32 %0, %1;" : "=r"(u) : "f"(x));
    return __uint_as_float(u);
}
__device__ __forceinline__ uint32_t smem_u32(const void* p) {
    uint32_t a;
    asm("{ .reg .u64 t; cvta.to.shared.u64 t, %1; cvt.u32.u64 %0, t; }" : "=r"(a) : "l"(p));
    return a;
}
__device__ __forceinline__ void cp16(uint32_t dst, const void* src) {
    asm volatile("cp.async.cg.shared.global [%0], [%1], 16;" :: "r"(dst), "l"(src));
}
__device__ __forceinline__ void cp_commit() {
    asm volatile("cp.async.commit_group;" ::: "memory");
}
template<int N> __device__ __forceinline__ void cp_wait() {
    asm volatile("cp.async.wait_group %0;" :: "n"(N) : "memory");
}

// ------------------------- generic tf32 WMMA GEMM (QKV / out proj) ----------
#define BK  32
#define LDS 40

template<int TILE_N, int NST, int MODE>   // MODE: 0 plain store, 1 tf32-rounded
__global__ void __launch_bounds__(256)
wmma_gemm(const float* __restrict__ A, const float* __restrict__ B, float* __restrict__ C,
          int K, int lda, int ldb, int ldc)
{
    constexpr int AELEM = 128 * LDS;
    constexpr int BELEM = TILE_N * LDS;
    constexpr int NB    = TILE_N / 64;

    extern __shared__ float sm[];
    float* sA = sm;
    float* sB = sm + (size_t)NST * AELEM;

    const int tid = threadIdx.x;
    const int wid = tid >> 5;
    const int warp_m = wid & 1;
    const int warp_n = wid >> 1;

    const int m0 = blockIdx.y * 128;
    const int n0 = blockIdx.x * TILE_N;
    const int nch = K >> 5;

    wmma::fragment<wmma::accumulator, 16, 16, 8, float> cf[4][NB];
    #pragma unroll
    for (int i = 0; i < 4; i++)
        #pragma unroll
        for (int j = 0; j < NB; j++)
            wmma::fill_fragment(cf[i][j], 0.0f);

    auto load = [&](int s, int c) {
        const int k0 = c * BK;
        uint32_t aB = smem_u32(sA + (size_t)s * AELEM);
        uint32_t bB = smem_u32(sB + (size_t)s * BELEM);
        #pragma unroll
        for (int j = 0; j < 4; j++) {
            int f = tid + j * 256, r = f >> 3, q = f & 7;
            cp16(aB + (uint32_t)(r * LDS + q * 4) * 4,
                 A + (size_t)(m0 + r) * lda + k0 + q * 4);
        }
        #pragma unroll
        for (int j = 0; j < TILE_N / 32; j++) {
            int f = tid + j * 256, r = f >> 3, q = f & 7;
            cp16(bB + (uint32_t)(r * LDS + q * 4) * 4,
                 B + (size_t)(n0 + r) * ldb + k0 + q * 4);
        }
        cp_commit();
    };

    const int P0 = (nch < NST - 1) ? nch : NST - 1;
    for (int c = 0; c < P0; c++) load(c, c);

    for (int c = 0; c < nch; c++) {
        const int s = c % NST;
        if (c + NST - 1 < nch) cp_wait<NST - 2>(); else cp_wait<0>();
        __syncthreads();
        if (c + NST - 1 < nch) load((c + NST - 1) % NST, c + NST - 1);

        const float* As = sA + (size_t)s * AELEM + warp_m * 64 * LDS;
        const float* Bs = sB + (size_t)s * BELEM + warp_n * (TILE_N / 4) * LDS;
        #pragma unroll
        for (int kc = 0; kc < 4; kc++) {
            wmma::fragment<wmma::matrix_a, 16, 16, 8, wmma::precision::tf32, wmma::row_major> af[4];
            wmma::fragment<wmma::matrix_b, 16, 16, 8, wmma::precision::tf32, wmma::col_major> bf[NB];
            #pragma unroll
            for (int i = 0; i < 4; i++)
                wmma::load_matrix_sync(af[i], As + i * 16 * LDS + kc * 8, LDS);
            #pragma unroll
            for (int j = 0; j < NB; j++)
                wmma::load_matrix_sync(bf[j], Bs + j * 16 * LDS + kc * 8, LDS);
            #pragma unroll
            for (int i = 0; i < 4; i++)
                #pragma unroll
                for (int j = 0; j < NB; j++)
                    wmma::mma_sync(cf[i][j], af[i], bf[j], cf[i][j]);
        }
        __syncthreads();
    }

    #pragma unroll
    for (int i = 0; i < 4; i++) {
        #pragma unroll
        for (int j = 0; j < NB; j++) {
            if (MODE == 1) {
                #pragma unroll
                for (int e = 0; e < 8; e++) cf[i][j].x[e] = tf32r(cf[i][j].x[e]);
            }
            float* Cp = C + (size_t)(m0 + warp_m * 64 + i * 16) * ldc
                          + n0 + warp_n * (TILE_N / 4) + j * 16;
            wmma::store_matrix_sync(Cp, cf[i][j], ldc, wmma::mem_row_major);
        }
    }
}

// ------------------------- fused attention (2-pass recompute) ---------------
// grid (SEQ/64, 32 z), 256 threads, 2 CTAs/SM.
// Pass 1: S=Q.K^T/8 per 64-kv chunk, exp, row sums (nothing to gmem).
// Pass 2: recompute S chunk, exp, normalize, write P once, O += P@V.
#define FLD 68

__global__ void __launch_bounds__(256, 2)
attn_kernel(const float* __restrict__ QKV, float* __restrict__ P, float* __restrict__ O)
{
    extern __shared__ float sm[];
    float* sQ  = sm;                     // [64][FLD]
    float* sE  = sQ + 64 * FLD;          // [64][FLD]
    float* sKV = sE + 64 * FLD;          // 2 buffers x (K[64][FLD] + V[64][FLD])
    __shared__ float sRow[64];
    __shared__ float sInv[64];

    const int tid = threadIdx.x;
    const int wid = tid >> 5;
    const int z = blockIdx.y, b = z >> 4, h = z & 15;
    const int q0 = blockIdx.x * 64;

    const float* Qb = QKV + (size_t)b * SEQ * QKVLD + h * DK;
    const float* Kb = QKV + (size_t)b * SEQ * QKVLD + D_MODEL + h * DK;
    const float* Vb = QKV + (size_t)b * SEQ * QKVLD + 2 * D_MODEL + h * DK;
    float* Pb = P + (size_t)z * SEQ * SEQ + (size_t)q0 * SEQ;

    // full 64x64 tile load: 4 x 256 threads x 16B = 16 KB
    auto prefetch = [&](int kt, bool withV) {
        float* buf = sKV + (kt & 1) * 2 * 64 * FLD;
        uint32_t kB = smem_u32(buf);
        #pragma unroll
        for (int j = 0; j < 4; j++) {
            int f = tid + j * 256, r = f >> 4, c4 = f & 15;
            cp16(kB + (uint32_t)(r * FLD + c4 * 4) * 4,
                 Kb + (size_t)(kt * 64 + r) * QKVLD + c4 * 4);
        }
        if (withV) {
            uint32_t vB = smem_u32(buf + 64 * FLD);
            #pragma unroll
            for (int j = 0; j < 4; j++) {
                int f = tid + j * 256, r = f >> 4, c4 = f & 15;
                cp16(vB + (uint32_t)(r * FLD + c4 * 4) * 4,
                     Vb + (size_t)(kt * 64 + r) * QKVLD + c4 * 4);
            }
        }
        cp_commit();
    };

    // Q tile load (merged into first commit group by prefetch(0))
    {
        uint32_t qB = smem_u32(sQ);
        #pragma unroll
        for (int j = 0; j < 4; j++) {
            int f = tid + j * 256, r = f >> 4, c4 = f & 15;
            cp16(qB + (uint32_t)(r * FLD + c4 * 4) * 4,
                 Qb + (size_t)(q0 + r) * QKVLD + c4 * 4);
        }
    }
    prefetch(0, false);
    prefetch(1, false);
    if (tid < 64) sRow[tid] = 0.f;

    const int wm = wid & 1, wn = wid >> 1;   // S/O warp tile: 32 rows x 16 cols

    // ---------------- pass 1: row sums ----------------
    for (int kt = 0; kt < 32; kt++) {
        float* sK = sKV + (kt & 1) * 2 * 64 * FLD;
        if (kt == 31) cp_wait<0>(); else cp_wait<1>();
        __syncthreads();

        wmma::fragment<wmma::accumulator, 16, 16, 8, float> acc[2];
        #pragma unroll
        for (int i = 0; i < 2; i++) wmma::fill_fragment(acc[i], 0.f);
        #pragma unroll
        for (int ks = 0; ks < 8; ks++) {
            wmma::fragment<wmma::matrix_b, 16, 16, 8, wmma::precision::tf32, wmma::col_major> bf;
            wmma::load_matrix_sync(bf, sK + (wn * 16) * FLD + ks * 8, FLD);
            #pragma unroll
            for (int i = 0; i < 2; i++) {
                wmma::fragment<wmma::matrix_a, 16, 16, 8, wmma::precision::tf32, wmma::row_major> af;
                wmma::load_matrix_sync(af, sQ + (wm * 32 + i * 16) * FLD + ks * 8, FLD);
                wmma::mma_sync(acc[i], af, bf, acc[i]);
            }
        }
        #pragma unroll
        for (int i = 0; i < 2; i++) {
            #pragma unroll
            for (int e = 0; e < 8; e++) acc[i].x[e] = __expf(acc[i].x[e] * 0.125f);
            wmma::store_matrix_sync(sE + (wm * 32 + i * 16) * FLD + wn * 16,
                                    acc[i], FLD, wmma::mem_row_major);
        }
        __syncthreads();

        // row-sum the 64x64 E tile: 4 threads per row, 16 cols each
        {
            const int r = tid >> 2, seg = tid & 3;
            const float* row = sE + r * FLD + seg * 16;
            float s = 0.f;
            #pragma unroll
            for (int c = 0; c < 16; c += 4)
                s += (row[c] + row[c + 1]) + (row[c + 2] + row[c + 3]);
            s += __shfl_xor_sync(0xFFFFFFFFu, s, 1);
            s += __shfl_xor_sync(0xFFFFFFFFu, s, 2);
            if (seg == 0) sRow[r] += s;
        }
        if (kt + 2 < 32) prefetch(kt + 2, false);
    }
    __syncthreads();
    if (tid < 64) sInv[tid] = 1.0f / sRow[tid];

    // restart pipeline with V
    prefetch(0, true);
    prefetch(1, true);

    wmma::fragment<wmma::accumulator, 16, 16, 8, float> accO[2];
    #pragma unroll
    for (int i = 0; i < 2; i++) wmma::fill_fragment(accO[i], 0.f);

    // ---------------- pass 2: recompute, normalize, write P, O += P@V -------
    for (int kt = 0; kt < 32; kt++) {
        float* sK = sKV + (kt & 1) * 2 * 64 * FLD;
        float* sV = sK + 64 * FLD;
        if (kt == 31) cp_wait<0>(); else cp_wait<1>();
        __syncthreads();

        wmma::fragment<wmma::accumulator, 16, 16, 8, float> acc[2];
        #pragma unroll
        for (int i = 0; i < 2; i++) wmma::fill_fragment(acc[i], 0.f);
        #pragma unroll
        for (int ks = 0; ks < 8; ks++) {
            wmma::fragment<wmma::matrix_b, 16, 16, 8, wmma::precision::tf32, wmma::col_major> bf;
            wmma::load_matrix_sync(bf, sK + (wn * 16) * FLD + ks * 8, FLD);
            #pragma unroll
            for (int i = 0; i < 2; i++) {
                wmma::fragment<wmma::matrix_a, 16, 16, 8, wmma::precision::tf32, wmma::row_major> af;
                wmma::load_matrix_sync(af, sQ + (wm * 32 + i * 16) * FLD + ks * 8, FLD);
                wmma::mma_sync(acc[i], af, bf, acc[i]);
            }
        }
        #pragma unroll
        for (int i = 0; i < 2; i++) {
            #pragma unroll
            for (int e = 0; e < 8; e++) acc[i].x[e] = __expf(acc[i].x[e] * 0.125f);
            wmma::store_matrix_sync(sE + (wm * 32 + i * 16) * FLD + wn * 16,
                                    acc[i], FLD, wmma::mem_row_major);
        }
        __syncthreads();

        // normalize + tf32-round in smem; write final P (coalesced)
        #pragma unroll
        for (int j = 0; j < 4; j++) {
            int f = tid + j * 256, r = f >> 4, c4 = f & 15;
            float4* sp = reinterpret_cast<float4*>(sE + r * FLD + c4 * 4);
            float4 v = *sp;
            const float iv = sInv[r];
            v.x = tf32r(v.x * iv); v.y = tf32r(v.y * iv);
            v.z = tf32r(v.z * iv); v.w = tf32r(v.w * iv);
            *sp = v;
            *reinterpret_cast<float4*>(Pb + (size_t)r * SEQ + kt * 64 + c4 * 4) = v;
        }
        __syncthreads();

        // O += P_chunk @ V_chunk (both from smem)
        #pragma unroll
        for (int ks = 0; ks < 8; ks++) {
            wmma::fragment<wmma::matrix_b, 16, 16, 8, wmma::precision::tf32, wmma::row_major> bf;
            wmma::load_matrix_sync(bf, sV + (ks * 8) * FLD + wn * 16, FLD);
            #pragma unroll
            for (int i = 0; i < 2; i++) {
                wmma::fragment<wmma::matrix_a, 16, 16, 8, wmma::precision::tf32, wmma::row_major> af;
                wmma::load_matrix_sync(af, sE + (wm * 32 + i * 16) * FLD + ks * 8, FLD);
                wmma::mma_sync(accO[i], af, bf, accO[i]);
            }
        }
        __syncthreads();            // all warps done reading this KV buffer
        if (kt + 2 < 32) prefetch(kt + 2, true);
    }

    #pragma unroll
    for (int i = 0; i < 2; i++) {
        #pragma unroll
        for (int e = 0; e < 8; e++) accO[i].x[e] = tf32r(accO[i].x[e]);
        float* Op = O + (size_t)(b * SEQ + q0 + wm * 32 + i * 16) * D_MODEL + h * DK + wn * 16;
        wmma::store_matrix_sync(Op, accO[i], D_MODEL, wmma::mem_row_major);
    }
}

// ------------------------- cvt kernels ---------------------------------------
__global__ void cvt_x_kernel(const float4* __restrict__ src, float4* __restrict__ dst, int n4)
{
    int i = blockIdx.x * blockDim.x + threadIdx.x;
    if (i < n4) {
        float4 v = src[i];
        v.x = tf32r(v.x); v.y = tf32r(v.y); v.z = tf32r(v.z); v.w = tf32r(v.w);
        dst[i] = v;
    }
}
__global__ void cvt_w_kernel(const float4* __restrict__ w0, const float4* __restrict__ w1,
                             const float4* __restrict__ w2, const float4* __restrict__ w3,
                             float4* __restrict__ dst)
{
    const int per = D_MODEL * D_MODEL / 4;
    int i = blockIdx.x * blockDim.x + threadIdx.x;
    const float4* src = (i < per) ? w0 : (i < 2 * per) ? w1 : (i < 3 * per) ? w2 : w3;
    float4 v = src[i & (per - 1)];
    v.x = tf32r(v.x); v.y = tf32r(v.y); v.z = tf32r(v.z); v.w = tf32r(v.w);
    dst[i] = v;
}

// ------------------------- host ----------------------------------------------
extern "C" void kernel_launch(void* const* d_in, const int* in_sizes, int n_in,
                              void* d_out, int out_size)
{
    const float* x  = (const float*)d_in[0];
    const float* Wq = (const float*)d_in[1];
    const float* Wk = (const float*)d_in[2];
    const float* Wv = (const float*)d_in[3];
    const float* Wo = (const float*)d_in[4];
    float* out = (float*)d_out;

    float *pxt, *pwt, *pQKV, *pO;
    cudaGetSymbolAddress((void**)&pxt,  g_xt);
    cudaGetSymbolAddress((void**)&pwt,  g_wt);
    cudaGetSymbolAddress((void**)&pQKV, g_QKV);
    cudaGetSymbolAddress((void**)&pO,   g_O);

    const size_t projN = (size_t)MTOT * D_MODEL;
    float* S = out + projN;   // attn_weights region of d_out
    const size_t M2 = (size_t)D_MODEL * D_MODEL;

    const int smemG = 3 * (128 + 128) * LDS * 4;             // 122880 (QKV/out GEMM)
    const int smemA = (2 * 64 * FLD + 2 * 2 * 64 * FLD) * 4; // 104448 (attention)
    cudaFuncSetAttribute(wmma_gemm<128, 3, 1>, cudaFuncAttributeMaxDynamicSharedMemorySize, smemG);
    cudaFuncSetAttribute(wmma_gemm<128, 3, 0>, cudaFuncAttributeMaxDynamicSharedMemorySize, smemG);
    cudaFuncSetAttribute(attn_kernel,          cudaFuncAttributeMaxDynamicSharedMemorySize, smemA);

    // 1) tf32-round inputs
    cvt_x_kernel<<<(int)(projN / 4 / 256), 256>>>((const float4*)x, (float4*)pxt, (int)(projN / 4));
    cvt_w_kernel<<<(int)(4 * M2 / 4 / 256), 256>>>((const float4*)Wq, (const float4*)Wk,
                                                   (const float4*)Wv, (const float4*)Wo, (float4*)pwt);

    // 2) fused QKV projection (tf32-rounded store)
    dim3 gqkv(QKVLD / 128, MTOT / 128);
    wmma_gemm<128, 3, 1><<<gqkv, 256, smemG>>>(pxt, pwt, pQKV, D_MODEL, D_MODEL, D_MODEL, QKVLD);

    // 3) fused attention: P (written once, normalized) + O
    attn_kernel<<<dim3(SEQ / 64, BATCH * N_HEADS), 256, smemA>>>(pQKV, S, pO);

    // 4) out = O @ Wo^T
    dim3 gproj(D_MODEL / 128, MTOT / 128);
    wmma_gemm<128, 3, 0><<<gproj, 256, smemG>>>(pO, pwt + 3 * M2, out, D_MODEL, D_MODEL, D_MODEL, D_MODEL);
}

// round 10
// speedup vs baseline: 1.1819x; 1.1819x over previous
#include <cuda_runtime.h>
#include <mma.h>
#include <cstdint>

using namespace nvcuda;

#define D_MODEL 1024
#define N_HEADS 16
#define DK      64
#define BATCH   2
#define SEQ     2048
#define MTOT    (BATCH*SEQ)
#define QKVLD   (3*D_MODEL)   // 3072

// ------------------------- scratch (no allocs allowed) ----------------------
__device__ float g_xt  [(size_t)MTOT * D_MODEL];           // tf32-rounded x
__device__ float g_wt  [(size_t)4 * D_MODEL * D_MODEL];    // tf32-rounded Wq,Wk,Wv,Wo
__device__ float g_QKV [(size_t)MTOT * QKVLD];             // fused Q|K|V, ld=3072
__device__ float g_O   [(size_t)MTOT * D_MODEL];
__device__ float g_part[(size_t)BATCH * N_HEADS * SEQ * 16]; // per-tile row sums
__device__ float g_inv [(size_t)BATCH * N_HEADS * SEQ];      // 1/rowsum

// ------------------------- helpers ------------------------------------------
__device__ __forceinline__ float tf32r(float x) {
    uint32_t u;
    asm("cvt.rna.tf32.f32 %0, %1;" : "=r"(u) : "f"(x));
    return __uint_as_float(u);
}
__device__ __forceinline__ uint32_t smem_u32(const void* p) {
    uint32_t a;
    asm("{ .reg .u64 t; cvta.to.shared.u64 t, %1; cvt.u32.u64 %0, t; }" : "=r"(a) : "l"(p));
    return a;
}
__device__ __forceinline__ void cp16(uint32_t dst, const void* src) {
    asm volatile("cp.async.cg.shared.global [%0], [%1], 16;" :: "r"(dst), "l"(src));
}
__device__ __forceinline__ void cp_commit() {
    asm volatile("cp.async.commit_group;" ::: "memory");
}
template<int N> __device__ __forceinline__ void cp_wait() {
    asm volatile("cp.async.wait_group %0;" :: "n"(N) : "memory");
}

// ------------------------- generic tf32 WMMA GEMM (QKV / out proj) ----------
// NST=2 double-buffer, 82 KB smem -> 2 CTAs/SM; reg-capped to 128.
#define BK  32
#define LDS 40
#define NST 2

template<int MODE>   // MODE: 0 plain store, 1 tf32-rounded
__global__ void __launch_bounds__(256, 2)
wmma_gemm(const float* __restrict__ A, const float* __restrict__ B, float* __restrict__ C,
          int K, int lda, int ldb, int ldc)
{
    constexpr int AELEM = 128 * LDS;
    constexpr int BELEM = 128 * LDS;

    extern __shared__ float sm[];
    float* sA = sm;
    float* sB = sm + (size_t)NST * AELEM;

    const int tid = threadIdx.x;
    const int wid = tid >> 5;
    const int warp_m = wid & 1;
    const int warp_n = wid >> 1;

    const int m0 = blockIdx.y * 128;
    const int n0 = blockIdx.x * 128;
    const int nch = K >> 5;

    wmma::fragment<wmma::accumulator, 16, 16, 8, float> cf[4][2];
    #pragma unroll
    for (int i = 0; i < 4; i++)
        #pragma unroll
        for (int j = 0; j < 2; j++)
            wmma::fill_fragment(cf[i][j], 0.0f);

    auto load = [&](int s, int c) {
        const int k0 = c * BK;
        uint32_t aB = smem_u32(sA + (size_t)s * AELEM);
        uint32_t bB = smem_u32(sB + (size_t)s * BELEM);
        #pragma unroll
        for (int j = 0; j < 4; j++) {
            int f = tid + j * 256, r = f >> 3, q = f & 7;
            cp16(aB + (uint32_t)(r * LDS + q * 4) * 4,
                 A + (size_t)(m0 + r) * lda + k0 + q * 4);
        }
        #pragma unroll
        for (int j = 0; j < 4; j++) {
            int f = tid + j * 256, r = f >> 3, q = f & 7;
            cp16(bB + (uint32_t)(r * LDS + q * 4) * 4,
                 B + (size_t)(n0 + r) * ldb + k0 + q * 4);
        }
        cp_commit();
    };

    load(0, 0);

    for (int c = 0; c < nch; c++) {
        const int s = c & 1;
        cp_wait<0>();
        __syncthreads();
        if (c + 1 < nch) load((c + 1) & 1, c + 1);

        const float* As = sA + (size_t)s * AELEM + warp_m * 64 * LDS;
        const float* Bs = sB + (size_t)s * BELEM + warp_n * 32 * LDS;
        #pragma unroll
        for (int kc = 0; kc < 4; kc++) {
            wmma::fragment<wmma::matrix_a, 16, 16, 8, wmma::precision::tf32, wmma::row_major> af[4];
            wmma::fragment<wmma::matrix_b, 16, 16, 8, wmma::precision::tf32, wmma::col_major> bf[2];
            #pragma unroll
            for (int i = 0; i < 4; i++)
                wmma::load_matrix_sync(af[i], As + i * 16 * LDS + kc * 8, LDS);
            #pragma unroll
            for (int j = 0; j < 2; j++)
                wmma::load_matrix_sync(bf[j], Bs + j * 16 * LDS + kc * 8, LDS);
            #pragma unroll
            for (int i = 0; i < 4; i++)
                #pragma unroll
                for (int j = 0; j < 2; j++)
                    wmma::mma_sync(cf[i][j], af[i], bf[j], cf[i][j]);
        }
        __syncthreads();
    }

    #pragma unroll
    for (int i = 0; i < 4; i++) {
        #pragma unroll
        for (int j = 0; j < 2; j++) {
            if (MODE == 1) {
                #pragma unroll
                for (int e = 0; e < 8; e++) cf[i][j].x[e] = tf32r(cf[i][j].x[e]);
            }
            float* Cp = C + (size_t)(m0 + warp_m * 64 + i * 16) * ldc
                          + n0 + warp_n * 32 + j * 16;
            wmma::store_matrix_sync(Cp, cf[i][j], ldc, wmma::mem_row_major);
        }
    }
}

// ------------------------- scores + exp + row partial sums -------------------
// grid (16 ntile, 16 qtile, 32 z), 256 threads, 3 CTAs/SM. (R6-proven, 461us)
#define SLD 68
#define ELD 132

__global__ void __launch_bounds__(256, 3)
scores_exp_kernel(const float* __restrict__ QKV, float* __restrict__ E,
                  float* __restrict__ partial)
{
    extern __shared__ float sm[];          // union: [Q 128*68 | K 128*68] / [E 128*132]
    float* sQ = sm;
    float* sK = sm + 128 * SLD;

    const int tid = threadIdx.x;
    const int wid = tid >> 5;
    const int z = blockIdx.z, b = z >> 4, h = z & 15;
    const int q0 = blockIdx.y * 128;
    const int n0 = blockIdx.x * 128;

    const float* Qb = QKV + (size_t)b * SEQ * QKVLD + h * DK;
    const float* Kb = QKV + (size_t)b * SEQ * QKVLD + D_MODEL + h * DK;

    {
        uint32_t qB = smem_u32(sQ), kB = smem_u32(sK);
        #pragma unroll
        for (int j = 0; j < 8; j++) {
            int f = tid + j * 256, r = f >> 4, c = f & 15;
            cp16(qB + (uint32_t)(r * SLD + c * 4) * 4, Qb + (size_t)(q0 + r) * QKVLD + c * 4);
        }
        #pragma unroll
        for (int j = 0; j < 8; j++) {
            int f = tid + j * 256, r = f >> 4, c = f & 15;
            cp16(kB + (uint32_t)(r * SLD + c * 4) * 4, Kb + (size_t)(n0 + r) * QKVLD + c * 4);
        }
        cp_commit();
        cp_wait<0>();
    }
    __syncthreads();

    const int wm = wid & 1, wn = wid >> 1;
    wmma::fragment<wmma::accumulator, 16, 16, 8, float> acc[4][2];
    #pragma unroll
    for (int i = 0; i < 4; i++)
        #pragma unroll
        for (int j = 0; j < 2; j++)
            wmma::fill_fragment(acc[i][j], 0.0f);

    #pragma unroll
    for (int ks = 0; ks < 8; ks++) {
        wmma::fragment<wmma::matrix_a, 16, 16, 8, wmma::precision::tf32, wmma::row_major> af[4];
        wmma::fragment<wmma::matrix_b, 16, 16, 8, wmma::precision::tf32, wmma::col_major> bf[2];
        #pragma unroll
        for (int i = 0; i < 4; i++)
            wmma::load_matrix_sync(af[i], sQ + (wm * 64 + i * 16) * SLD + ks * 8, SLD);
        #pragma unroll
        for (int j = 0; j < 2; j++)
            wmma::load_matrix_sync(bf[j], sK + (wn * 32 + j * 16) * SLD + ks * 8, SLD);
        #pragma unroll
        for (int i = 0; i < 4; i++)
            #pragma unroll
            for (int j = 0; j < 2; j++)
                wmma::mma_sync(acc[i][j], af[i], bf[j], acc[i][j]);
    }
    __syncthreads();   // smem union: done with Q/K

    #pragma unroll
    for (int i = 0; i < 4; i++)
        #pragma unroll
        for (int j = 0; j < 2; j++) {
            #pragma unroll
            for (int e = 0; e < 8; e++) acc[i][j].x[e] = __expf(acc[i][j].x[e] * 0.125f);
            wmma::store_matrix_sync(sm + (wm * 64 + i * 16) * ELD + wn * 32 + j * 16,
                                    acc[i][j], ELD, wmma::mem_row_major);
        }
    __syncthreads();

    float* Eb = E + (size_t)z * SEQ * SEQ + (size_t)q0 * SEQ + n0;
    #pragma unroll
    for (int j = 0; j < 16; j++) {
        int f = tid + j * 256, rr = f >> 5, c4 = f & 31;
        *reinterpret_cast<float4*>(Eb + (size_t)rr * SEQ + c4 * 4) =
            *reinterpret_cast<const float4*>(sm + rr * ELD + c4 * 4);
    }
    {
        const int r = tid >> 1, hf = tid & 1;
        const float* row = sm + r * ELD + hf * 64;
        float s = 0.f;
        #pragma unroll
        for (int c = 0; c < 64; c += 4)
            s += (row[c] + row[c + 1]) + (row[c + 2] + row[c + 3]);
        s += __shfl_xor_sync(0xFFFFFFFFu, s, 1);
        if (!hf) partial[((size_t)z * SEQ + q0 + r) * 16 + blockIdx.x] = s;
    }
}

// ------------------------- reduce partials -> 1/rowsum -----------------------
__global__ void rowinv_kernel(const float* __restrict__ partial, float* __restrict__ inv)
{
    int i = blockIdx.x * 256 + threadIdx.x;   // 65536 rows
    const float4* p = reinterpret_cast<const float4*>(partial + (size_t)i * 16);
    float4 a = p[0], b = p[1], c = p[2], d = p[3];
    float s = (((a.x + a.y) + (a.z + a.w)) + ((b.x + b.y) + (b.z + b.w)))
            + (((c.x + c.y) + (c.z + c.w)) + ((d.x + d.y) + (d.z + d.w)));
    inv[i] = 1.0f / s;
}

// ------------------------- normalize (write P) + P@V -------------------------
// grid (32 qtile, 32 z), 256 threads, 3 CTAs/SM. CTA: 64 q rows.
// E and V both staged in smem (coalesced), double-buffered 64-kv chunks.
#define PVLD 68

__global__ void __launch_bounds__(256, 3)
pv_kernel(float* __restrict__ E, const float* __restrict__ QKV,
          const float* __restrict__ inv, float* __restrict__ O)
{
    extern __shared__ float sm[];            // sE[2][64][68] + sV[2][64][68]
    __shared__ float sinv[64];
    float* sE[2] = { sm,                sm + 64 * PVLD };
    float* sV[2] = { sm + 2 * 64 * PVLD, sm + 3 * 64 * PVLD };

    const int tid = threadIdx.x;
    const int wid = tid >> 5;
    const int z = blockIdx.y, b = z >> 4, h = z & 15;
    const int q0 = blockIdx.x * 64;

    float* Eb = E + (size_t)z * SEQ * SEQ + (size_t)q0 * SEQ;
    const float* Vb = QKV + (size_t)b * SEQ * QKVLD + 2 * D_MODEL + h * DK;

    if (tid < 64) sinv[tid] = inv[(size_t)z * SEQ + q0 + tid];

    auto prefetch = [&](int kt) {
        uint32_t eB = smem_u32(sE[kt & 1]);
        uint32_t vB = smem_u32(sV[kt & 1]);
        #pragma unroll
        for (int j = 0; j < 4; j++) {
            int f = tid + j * 256, r = f >> 4, c4 = f & 15;
            cp16(eB + (uint32_t)(r * PVLD + c4 * 4) * 4,
                 Eb + (size_t)r * SEQ + kt * 64 + c4 * 4);
        }
        #pragma unroll
        for (int j = 0; j < 4; j++) {
            int f = tid + j * 256, r = f >> 4, c4 = f & 15;
            cp16(vB + (uint32_t)(r * PVLD + c4 * 4) * 4,
                 Vb + (size_t)(kt * 64 + r) * QKVLD + c4 * 4);
        }
        cp_commit();
    };
    prefetch(0);
    prefetch(1);

    const int wm = wid & 1, wn = wid >> 1;   // O(64x64): warp tile 32q x 16d
    wmma::fragment<wmma::accumulator, 16, 16, 8, float> acc[2];
    #pragma unroll
    for (int i = 0; i < 2; i++) wmma::fill_fragment(acc[i], 0.f);

    for (int kt = 0; kt < 32; kt++) {
        float* bufE = sE[kt & 1];
        float* bufV = sV[kt & 1];
        if (kt < 31) cp_wait<1>(); else cp_wait<0>();
        __syncthreads();

        // normalize + tf32-round in smem; write final P to gmem (coalesced)
        #pragma unroll
        for (int j = 0; j < 4; j++) {
            int f = tid + j * 256, r = f >> 4, c4 = f & 15;
            float4* sp = reinterpret_cast<float4*>(bufE + r * PVLD + c4 * 4);
            float4 v = *sp;
            const float iv = sinv[r];
            v.x = tf32r(v.x * iv); v.y = tf32r(v.y * iv);
            v.z = tf32r(v.z * iv); v.w = tf32r(v.w * iv);
            *sp = v;
            *reinterpret_cast<float4*>(Eb + (size_t)r * SEQ + kt * 64 + c4 * 4) = v;
        }
        __syncthreads();

        // O += P_chunk @ V_chunk (both operands from smem)
        #pragma unroll
        for (int ks = 0; ks < 8; ks++) {
            wmma::fragment<wmma::matrix_b, 16, 16, 8, wmma::precision::tf32, wmma::row_major> bf;
            wmma::load_matrix_sync(bf, bufV + (ks * 8) * PVLD + wn * 16, PVLD);
            #pragma unroll
            for (int i = 0; i < 2; i++) {
                wmma::fragment<wmma::matrix_a, 16, 16, 8, wmma::precision::tf32, wmma::row_major> af;
                wmma::load_matrix_sync(af, bufE + (wm * 32 + i * 16) * PVLD + ks * 8, PVLD);
                wmma::mma_sync(acc[i], af, bf, acc[i]);
            }
        }
        __syncthreads();
        if (kt + 2 < 32) prefetch(kt + 2);
    }

    #pragma unroll
    for (int i = 0; i < 2; i++) {
        #pragma unroll
        for (int e = 0; e < 8; e++) acc[i].x[e] = tf32r(acc[i].x[e]);
        float* Op = O + (size_t)(b * SEQ + q0 + wm * 32 + i * 16) * D_MODEL + h * DK + wn * 16;
        wmma::store_matrix_sync(Op, acc[i], D_MODEL, wmma::mem_row_major);
    }
}

// ------------------------- cvt kernels ---------------------------------------
__global__ void cvt_x_kernel(const float4* __restrict__ src, float4* __restrict__ dst, int n4)
{
    int i = blockIdx.x * blockDim.x + threadIdx.x;
    if (i < n4) {
        float4 v = src[i];
        v.x = tf32r(v.x); v.y = tf32r(v.y); v.z = tf32r(v.z); v.w = tf32r(v.w);
        dst[i] = v;
    }
}
__global__ void cvt_w_kernel(const float4* __restrict__ w0, const float4* __restrict__ w1,
                             const float4* __restrict__ w2, const float4* __restrict__ w3,
                             float4* __restrict__ dst)
{
    const int per = D_MODEL * D_MODEL / 4;
    int i = blockIdx.x * blockDim.x + threadIdx.x;
    const float4* src = (i < per) ? w0 : (i < 2 * per) ? w1 : (i < 3 * per) ? w2 : w3;
    float4 v = src[i & (per - 1)];
    v.x = tf32r(v.x); v.y = tf32r(v.y); v.z = tf32r(v.z); v.w = tf32r(v.w);
    dst[i] = v;
}

// ------------------------- host ----------------------------------------------
extern "C" void kernel_launch(void* const* d_in, const int* in_sizes, int n_in,
                              void* d_out, int out_size)
{
    const float* x  = (const float*)d_in[0];
    const float* Wq = (const float*)d_in[1];
    const float* Wk = (const float*)d_in[2];
    const float* Wv = (const float*)d_in[3];
    const float* Wo = (const float*)d_in[4];
    float* out = (float*)d_out;

    float *pxt, *pwt, *pQKV, *pO, *ppart, *pinv;
    cudaGetSymbolAddress((void**)&pxt,   g_xt);
    cudaGetSymbolAddress((void**)&pwt,   g_wt);
    cudaGetSymbolAddress((void**)&pQKV,  g_QKV);
    cudaGetSymbolAddress((void**)&pO,    g_O);
    cudaGetSymbolAddress((void**)&ppart, g_part);
    cudaGetSymbolAddress((void**)&pinv,  g_inv);

    const size_t projN = (size_t)MTOT * D_MODEL;
    float* S = out + projN;   // attn_weights region (E -> P in place)
    const size_t M2 = (size_t)D_MODEL * D_MODEL;

    const int smemG  = NST * (128 + 128) * LDS * 4;          //  81920 (proj GEMMs)
    const int smemSC = 2 * 128 * SLD * 4;                    //  69632 (scores union)
    const int smemPV = 4 * 64 * PVLD * 4;                    //  69632 (pv)
    cudaFuncSetAttribute(wmma_gemm<1>,      cudaFuncAttributeMaxDynamicSharedMemorySize, smemG);
    cudaFuncSetAttribute(wmma_gemm<0>,      cudaFuncAttributeMaxDynamicSharedMemorySize, smemG);
    cudaFuncSetAttribute(scores_exp_kernel, cudaFuncAttributeMaxDynamicSharedMemorySize, smemSC);
    cudaFuncSetAttribute(pv_kernel,         cudaFuncAttributeMaxDynamicSharedMemorySize, smemPV);

    // 1) tf32-round inputs
    cvt_x_kernel<<<(int)(projN / 4 / 256), 256>>>((const float4*)x, (float4*)pxt, (int)(projN / 4));
    cvt_w_kernel<<<(int)(4 * M2 / 4 / 256), 256>>>((const float4*)Wq, (const float4*)Wk,
                                                   (const float4*)Wv, (const float4*)Wo, (float4*)pwt);

    // 2) fused QKV projection (tf32-rounded store)
    dim3 gqkv(QKVLD / 128, MTOT / 128);
    wmma_gemm<1><<<gqkv, 256, smemG>>>(pxt, pwt, pQKV, D_MODEL, D_MODEL, D_MODEL, QKVLD);

    // 3) E = exp(QK^T/8) + per-tile row sums
    scores_exp_kernel<<<dim3(16, 16, BATCH * N_HEADS), 256, smemSC>>>(pQKV, S, ppart);

    // 4) 1/rowsum
    rowinv_kernel<<<BATCH * N_HEADS * SEQ / 256, 256>>>(ppart, pinv);

    // 5) normalize (write P in place) + O = P @ V
    pv_kernel<<<dim3(SEQ / 64, BATCH * N_HEADS), 256, smemPV>>>(S, pQKV, pinv, pO);

    // 6) out = O @ Wo^T
    dim3 gproj(D_MODEL / 128, MTOT / 128);
    wmma_gemm<0><<<gproj, 256, smemG>>>(pO, pwt + 3 * M2, out, D_MODEL, D_MODEL, D_MODEL, D_MODEL);
}